// round 4
// baseline (speedup 1.0000x reference)
#include <cuda_runtime.h>

#define NCLS 14
#define MAXP 32
#define MAXN 64
#define PREF 9       // 288-row speculative fast path (mean 96 pos/neg vs need 64: ~4 sigma)
#define TPB  512     // 16 warps per block -> 4 pair iters/thread

// Single packed accumulator, zero-init. Layout:
//   bits [0:8)   block-arrival counter (max 14)
//   bits [8:16)  active-class counter  (max 14)
//   bits [16:64) loss sum, fixed point, scale 2^36 (exact, order-independent add)
__device__ unsigned long long g_acc;

#define FX_SCALE 68719476736.0   // 2^36

// branch-free softplus(x) = max(x,0) + log(1 + exp(-|x|)); MUFU only
__device__ __forceinline__ float softplus_fast(float x) {
    return fmaxf(x, 0.f) + __logf(1.f + __expf(-fabsf(x)));
}

__global__ __launch_bounds__(TPB)
void pauc_kernel(const float* __restrict__ logits,
                 const int*   __restrict__ targets,
                 float* __restrict__ out,
                 int Bn) {
    __shared__ float pos_buf[MAXP];
    __shared__ float neg_buf[MAXN];
    __shared__ int   s_tp, s_tn;
    __shared__ float warp_sum[TPB / 32];

    const int c    = blockIdx.x;          // class
    const int tid  = threadIdx.x;
    const int w    = tid >> 5;
    const int lane = tid & 31;

    // ---- phase 1: warp 0 scans for first MAXP positives / MAXN negatives ----
    if (w == 0) {
        int npos = 0, nneg = 0;
        const unsigned below = (1u << lane) - 1u;

        int   tv[PREF];
        float lv[PREF];
#pragma unroll
        for (int k = 0; k < PREF; k++) {
            int row = k * 32 + lane;
            if (row < Bn) {
                tv[k] = targets[row * NCLS + c];
                lv[k] = logits [row * NCLS + c];
            } else { tv[k] = -1; lv[k] = 0.f; }
        }
#pragma unroll
        for (int k = 0; k < PREF; k++) {
            unsigned pm = __ballot_sync(0xffffffffu, tv[k] == 1);
            unsigned nm = __ballot_sync(0xffffffffu, tv[k] == 0);
            if (tv[k] == 1) {
                int r = npos + __popc(pm & below);
                if (r < MAXP) pos_buf[r] = lv[k];
            }
            if (tv[k] == 0) {
                int r = nneg + __popc(nm & below);
                if (r < MAXN) neg_buf[r] = lv[k];
            }
            npos += __popc(pm);
            nneg += __popc(nm);
        }

        // slow path (statistically never taken; required for exactness)
        int base = PREF * 32;
        while ((npos < MAXP || nneg < MAXN) && base < Bn) {
            int row = base + lane;
            int t = -1; float l = 0.f;
            if (row < Bn) {
                t = targets[row * NCLS + c];
                l = logits [row * NCLS + c];
            }
            unsigned pm = __ballot_sync(0xffffffffu, t == 1);
            unsigned nm = __ballot_sync(0xffffffffu, t == 0);
            if (t == 1) {
                int r = npos + __popc(pm & below);
                if (r < MAXP) pos_buf[r] = l;
            }
            if (t == 0) {
                int r = nneg + __popc(nm & below);
                if (r < MAXN) neg_buf[r] = l;
            }
            npos += __popc(pm);
            nneg += __popc(nm);
            base += 32;
        }
        if (lane == 0) { s_tp = min(npos, MAXP); s_tn = min(nneg, MAXN); }
    }
    __syncthreads();

    const int tp = s_tp, tn = s_tn;

    // ---- phase 2: all 16 warps share the tp x tn pair loss ----
    float s0 = 0.f, s1 = 0.f;
    if (tp == MAXP && tn == MAXN) {
        // common case: 2048 pairs, 4 per thread, shift/mask indexing, 2 accumulators
#pragma unroll
        for (int u = 0; u < (MAXP * MAXN) / TPB; u += 2) {
            int i0 = tid + u * TPB;
            int i1 = tid + (u + 1) * TPB;
            s0 += softplus_fast(neg_buf[i0 & (MAXN - 1)] - pos_buf[i0 >> 6]);
            s1 += softplus_fast(neg_buf[i1 & (MAXN - 1)] - pos_buf[i1 >> 6]);
        }
    } else {
        const int total = tp * tn;
        for (int idx = tid; idx < total; idx += TPB) {
            int i = idx / tn;
            int j = idx - i * tn;
            s0 += softplus_fast(neg_buf[j] - pos_buf[i]);
        }
    }
    float s = s0 + s1;
#pragma unroll
    for (int off = 16; off; off >>= 1)
        s += __shfl_xor_sync(0xffffffffu, s, off);
    if (lane == 0) warp_sum[w] = s;
    __syncthreads();

    // ---- phase 3: single packed-atomic epilogue ----
    if (tid == 0) {
        float bs = 0.f;
#pragma unroll
        for (int i = 0; i < TPB / 32; i++) bs += warp_sum[i];
        bool act = (tp > 0) && (tn > 0);
        float loss = act ? bs / (float)max(tp * tn, 1) : 0.f;

        unsigned long long fx = (unsigned long long)((double)loss * FX_SCALE + 0.5);
        unsigned long long pk = 1ull
                              | ((unsigned long long)(act ? 1 : 0) << 8)
                              | (fx << 16);
        unsigned long long tot = atomicAdd(&g_acc, pk) + pk;
        if ((tot & 0xFFull) == (unsigned long long)NCLS) {   // last block of this launch
            unsigned cnt = (unsigned)((tot >> 8) & 0xFFull);
            double ls = (double)(tot >> 16) * (1.0 / FX_SCALE);
            out[0] = (cnt > 0) ? (float)(ls / (double)cnt) : 0.f;
            // reset for next graph replay; we are the only block still running,
            // and kernel-completion ordering publishes this before the next launch
            *((volatile unsigned long long*)&g_acc) = 0ull;
        }
    }
}

extern "C" void kernel_launch(void* const* d_in, const int* in_sizes, int n_in,
                              void* d_out, int out_size) {
    const float* logits  = (const float*)d_in[0];
    const int*   targets = (const int*)  d_in[1];
    float*       out     = (float*)d_out;
    int Bn = in_sizes[0] / NCLS;
    pauc_kernel<<<NCLS, TPB>>>(logits, targets, out, Bn);
}

// round 5
// speedup vs baseline: 1.0294x; 1.0294x over previous
#include <cuda_runtime.h>

#define NCLS 14
#define MAXP 32
#define MAXN 64
#define PREF 9       // 288-row speculative fast path
#define TPB  512     // 16 warps per block -> 4 pair iters/thread

// Single packed accumulator, zero-init. Layout:
//   bits [0:8)   block-arrival counter (max 14)
//   bits [8:16)  active-class counter  (max 14)
//   bits [16:64) loss sum, fixed point, scale 2^36 (exact, order-independent)
__device__ unsigned long long g_acc;

#define FX_SCALE 68719476736.0   // 2^36

// branch-free softplus(x) = max(x,0) + log(1 + exp(-|x|)); MUFU only
__device__ __forceinline__ float softplus_fast(float x) {
    return fmaxf(x, 0.f) + __logf(1.f + __expf(-fabsf(x)));
}

__global__ __launch_bounds__(TPB)
void pauc_kernel(const float* __restrict__ logits,
                 const int*   __restrict__ targets,
                 float* __restrict__ out,
                 int Bn) {
    __shared__ float pos_buf[MAXP];
    __shared__ float neg_buf[MAXN];
    __shared__ int   s_tp, s_tn;
    __shared__ float warp_sum[TPB / 32];

    const int c    = blockIdx.x;          // class
    const int tid  = threadIdx.x;
    const int w    = tid >> 5;
    const int lane = tid & 31;

    // ---- phase 1: warp 0 scans for first MAXP positives / MAXN negatives ----
    if (w == 0) {
        int npos = 0, nneg = 0;
        const unsigned below = (1u << lane) - 1u;

        int   tv[PREF];
        float lv[PREF];
#pragma unroll
        for (int k = 0; k < PREF; k++) {
            int row = k * 32 + lane;
            if (row < Bn) {
                tv[k] = targets[row * NCLS + c];
                lv[k] = logits [row * NCLS + c];
            } else { tv[k] = -1; lv[k] = 0.f; }
        }
#pragma unroll
        for (int k = 0; k < PREF; k++) {
            unsigned pm = __ballot_sync(0xffffffffu, tv[k] == 1);
            unsigned nm = __ballot_sync(0xffffffffu, tv[k] == 0);
            if (tv[k] == 1) {
                int r = npos + __popc(pm & below);
                if (r < MAXP) pos_buf[r] = lv[k];
            }
            if (tv[k] == 0) {
                int r = nneg + __popc(nm & below);
                if (r < MAXN) neg_buf[r] = lv[k];
            }
            npos += __popc(pm);
            nneg += __popc(nm);
        }

        // slow path (statistically never taken; required for exactness)
        int base = PREF * 32;
        while ((npos < MAXP || nneg < MAXN) && base < Bn) {
            int row = base + lane;
            int t = -1; float l = 0.f;
            if (row < Bn) {
                t = targets[row * NCLS + c];
                l = logits [row * NCLS + c];
            }
            unsigned pm = __ballot_sync(0xffffffffu, t == 1);
            unsigned nm = __ballot_sync(0xffffffffu, t == 0);
            if (t == 1) {
                int r = npos + __popc(pm & below);
                if (r < MAXP) pos_buf[r] = l;
            }
            if (t == 0) {
                int r = nneg + __popc(nm & below);
                if (r < MAXN) neg_buf[r] = l;
            }
            npos += __popc(pm);
            nneg += __popc(nm);
            base += 32;
        }
        if (lane == 0) { s_tp = min(npos, MAXP); s_tn = min(nneg, MAXN); }
    }
    __syncthreads();

    const int tp = s_tp, tn = s_tn;

    // ---- phase 2: all 16 warps share the tp x tn pair loss ----
    float s0 = 0.f, s1 = 0.f, s2 = 0.f, s3 = 0.f;
    if (tp == MAXP && tn == MAXN) {
        // common case: 2048 pairs, 4 per thread, 4 independent MUFU chains
        int i0 = tid;
        int i1 = tid + TPB;
        int i2 = tid + 2 * TPB;
        int i3 = tid + 3 * TPB;
        s0 = softplus_fast(neg_buf[i0 & (MAXN - 1)] - pos_buf[i0 >> 6]);
        s1 = softplus_fast(neg_buf[i1 & (MAXN - 1)] - pos_buf[i1 >> 6]);
        s2 = softplus_fast(neg_buf[i2 & (MAXN - 1)] - pos_buf[i2 >> 6]);
        s3 = softplus_fast(neg_buf[i3 & (MAXN - 1)] - pos_buf[i3 >> 6]);
    } else {
        const int total = tp * tn;
        for (int idx = tid; idx < total; idx += TPB) {
            int i = idx / tn;
            int j = idx - i * tn;
            s0 += softplus_fast(neg_buf[j] - pos_buf[i]);
        }
    }
    float s = (s0 + s1) + (s2 + s3);
#pragma unroll
    for (int off = 16; off; off >>= 1)
        s += __shfl_xor_sync(0xffffffffu, s, off);
    if (lane == 0) warp_sum[w] = s;
    __syncthreads();

    // ---- phase 3: warp-parallel final reduce + single packed atomic ----
    if (w == 0) {
        float bs = (lane < TPB / 32) ? warp_sum[lane] : 0.f;
#pragma unroll
        for (int off = 8; off; off >>= 1)
            bs += __shfl_xor_sync(0xffffffffu, bs, off);
        if (lane == 0) {
            bool act = (tp > 0) && (tn > 0);
            float loss = act ? bs / (float)max(tp * tn, 1) : 0.f;

            unsigned long long fx = (unsigned long long)((double)loss * FX_SCALE + 0.5);
            unsigned long long pk = 1ull
                                  | ((unsigned long long)(act ? 1 : 0) << 8)
                                  | (fx << 16);
            unsigned long long tot = atomicAdd(&g_acc, pk) + pk;
            if ((tot & 0xFFull) == (unsigned long long)NCLS) { // last block this launch
                unsigned cnt = (unsigned)((tot >> 8) & 0xFFull);
                double ls = (double)(tot >> 16) * (1.0 / FX_SCALE);
                out[0] = (cnt > 0) ? (float)(ls / (double)cnt) : 0.f;
                // reset for next graph replay; only block still running, and
                // kernel-completion ordering publishes this before next launch
                g_acc = 0ull;
            }
        }
    }
}

extern "C" void kernel_launch(void* const* d_in, const int* in_sizes, int n_in,
                              void* d_out, int out_size) {
    const float* logits  = (const float*)d_in[0];
    const int*   targets = (const int*)  d_in[1];
    float*       out     = (float*)d_out;
    int Bn = in_sizes[0] / NCLS;
    pauc_kernel<<<NCLS, TPB>>>(logits, targets, out, Bn);
}